// round 16
// baseline (speedup 1.0000x reference)
#include <cuda_runtime.h>
#include <cuda_fp16.h>
#include <cstdint>
#include <math.h>

#define B_  2
#define S_  2048
#define D_  1024
#define H_  16
#define HD_ 64
#define EPS 1e-6f

#define ROWS (B_ * S_)          // 4096

// ---------------- scratch (device globals; no allocation) ----------------
__device__ __half g_xn  [ROWS * D_];
__device__ __half g_wqT [3 * D_ * D_];   // [3072][1024] K-major fp16
__device__ __half g_woT [D_ * D_];       // [1024][1024] K-major
__device__ __half g_qf[B_ * H_ * S_ * HD_];
__device__ __half g_kf[B_ * H_ * S_ * HD_];
__device__ __half g_vf[B_ * H_ * S_ * HD_];
__device__ __half g_attn[ROWS * D_];
__device__ float  g_ropeC[S_ * 32];
__device__ float  g_ropeS[S_ * 32];

// ================= helpers =================
__device__ __forceinline__ uint32_t smem_to_u32(const void* p) {
    uint32_t a;
    asm("{ .reg .u64 t; cvta.to.shared.u64 t, %1; cvt.u32.u64 %0, t; }"
        : "=r"(a) : "l"(p));
    return a;
}
__device__ __forceinline__ void cp16(void* sp, const void* gp) {
    uint32_t s = smem_to_u32(sp);
    asm volatile("cp.async.cg.shared.global [%0], [%1], 16;" :: "r"(s), "l"(gp));
}
#define CP_COMMIT() asm volatile("cp.async.commit_group;" ::: "memory")
#define CP_WAIT1()  asm volatile("cp.async.wait_group 1;"  ::: "memory")
#define CP_WAIT0()  asm volatile("cp.async.wait_group 0;"  ::: "memory")

__device__ __forceinline__ void mma16816(float* c, const uint32_t* a, const uint32_t* b) {
    asm volatile(
        "mma.sync.aligned.m16n8k16.row.col.f32.f16.f16.f32 "
        "{%0,%1,%2,%3}, {%4,%5,%6,%7}, {%8,%9}, {%0,%1,%2,%3};"
        : "+f"(c[0]), "+f"(c[1]), "+f"(c[2]), "+f"(c[3])
        : "r"(a[0]), "r"(a[1]), "r"(a[2]), "r"(a[3]),
          "r"(b[0]), "r"(b[1]));
}
__device__ __forceinline__ void ldsm_x4(uint32_t* r, uint32_t saddr) {
    asm volatile("ldmatrix.sync.aligned.m8n8.x4.shared.b16 {%0,%1,%2,%3}, [%4];"
        : "=r"(r[0]), "=r"(r[1]), "=r"(r[2]), "=r"(r[3]) : "r"(saddr));
}
__device__ __forceinline__ void ldsm_x4_t(uint32_t* r, uint32_t saddr) {
    asm volatile("ldmatrix.sync.aligned.m8n8.x4.trans.shared.b16 {%0,%1,%2,%3}, [%4];"
        : "=r"(r[0]), "=r"(r[1]), "=r"(r[2]), "=r"(r[3]) : "r"(saddr));
}
__device__ __forceinline__ uint32_t h2u(__half2 v) { return *(uint32_t*)&v; }

#define SW128(o) ((o) ^ (((o) >> 3) & 0x70))

// ---------------- block reduce (256 threads) ----------------
__device__ __forceinline__ float block_reduce_256(float v, float* sh) {
    #pragma unroll
    for (int o = 16; o; o >>= 1) v += __shfl_down_sync(0xffffffffu, v, o);
    if ((threadIdx.x & 31) == 0) sh[threadIdx.x >> 5] = v;
    __syncthreads();
    if (threadIdx.x == 0) {
        float t = 0.f;
        #pragma unroll
        for (int i = 0; i < 8; i++) t += sh[i];
        sh[0] = t;
    }
    __syncthreads();
    float r = sh[0];
    __syncthreads();
    return r;
}

// ---------------- fused prep: LN + weight transpose/cast + rope tables ----------------
#define PREP_BLOCKS (ROWS + 3072 + 1024 + 64)
__global__ __launch_bounds__(256) void prep_kernel(
    const float* __restrict__ x, const float* __restrict__ scale,
    const float* __restrict__ bias, __half* __restrict__ xn,
    const float* __restrict__ Wq, __half* __restrict__ WqT,
    const float* __restrict__ Wo, __half* __restrict__ WoT,
    float* __restrict__ ropeC, float* __restrict__ ropeS)
{
    __shared__ float shred[8];
    __shared__ float t[32][33];
    int bid = blockIdx.x;
    int tid = threadIdx.x;

    if (bid < ROWS) {
        int row = bid;
        const float4* xr = (const float4*)(x + (size_t)row * D_);
        float4 v = xr[tid];

        float s = v.x + v.y + v.z + v.w;
        float tot = block_reduce_256(s, shred);
        float mu = tot * (1.0f / D_);

        float dx = v.x - mu, dy = v.y - mu, dz = v.z - mu, dw = v.w - mu;
        float sq = dx*dx + dy*dy + dz*dz + dw*dw;
        float vtot = block_reduce_256(sq, shred);
        float rstd = rsqrtf(vtot * (1.0f / D_) + EPS);

        float4 sc = ((const float4*)scale)[tid];
        float4 bi = ((const float4*)bias)[tid];
        size_t base = (size_t)row * D_ + tid * 4;
        *(__half2*)&xn[base + 0] = __floats2half2_rn(dx * rstd * sc.x + bi.x,
                                                     dy * rstd * sc.y + bi.y);
        *(__half2*)&xn[base + 2] = __floats2half2_rn(dz * rstd * sc.z + bi.z,
                                                     dw * rstd * sc.w + bi.w);
    } else if (bid < ROWS + 3072 + 1024) {
        const float* W; __half* T; int K, N, tt;
        if (bid < ROWS + 3072) {
            tt = bid - ROWS; W = Wq; T = WqT; K = D_; N = 3 * D_;
        } else {
            tt = bid - ROWS - 3072; W = Wo; T = WoT; K = D_; N = D_;
        }
        int ntiles = N >> 5;
        int nb = (tt % ntiles) * 32, kb = (tt / ntiles) * 32;
        int tx = tid & 31, ty = tid >> 5;
        #pragma unroll
        for (int i = 0; i < 4; i++)
            t[ty + 8 * i][tx] = W[(size_t)(kb + ty + 8 * i) * N + nb + tx];
        __syncthreads();
        #pragma unroll
        for (int i = 0; i < 4; i++) {
            int n = nb + ty + 8 * i, k = kb + tx;
            T[(size_t)n * K + k] = __float2half(t[tx][ty + 8 * i]);
        }
    } else {
        int base = (bid - (ROWS + 3072 + 1024)) * 1024 + tid * 4;
        #pragma unroll
        for (int e = 0; e < 4; e++) {
            int idx = base + e;
            int s = idx >> 5, d = idx & 31;
            float inv = expf(-(float)(2 * d) * (1.0f / 64.0f) * 9.210340371976184f);
            float sn, cs;
            sincosf((float)s * inv, &sn, &cs);
            ropeC[idx] = cs;
            ropeS[idx] = sn;
        }
    }
}

// ---------------- shared GEMM machinery (single fp16, K-slab 64) ----------------
#define GT_BYTES 16384                       // one 128x64 fp16 tile
#define GSTAGE   (2 * GT_BYTES)              // Af, Bf
#define GEMM_SMEM (3 * GSTAGE)               // 98304

__device__ __forceinline__ void gemm_issue_stage(
    char* st,
    const __half* __restrict__ Af, const __half* __restrict__ Bf,
    int m0, int n0, int K, int kc, int tid)
{
    const __half* srcs[2] = {Af, Bf};
    const int row0s[2] = {m0, n0};
    #pragma unroll
    for (int t = 0; t < 2; t++) {
        #pragma unroll
        for (int i = 0; i < 4; i++) {
            int u = tid + i * 256;
            int r = u >> 3, c = u & 7;
            uint32_t off = (uint32_t)(r * 128 + c * 16);
            cp16(st + t * GT_BYTES + SW128(off),
                 srcs[t] + (size_t)(row0s[t] + r) * K + kc + c * 8);
        }
    }
}

#define GEMM_MAINLOOP(Af, Bf, m0, n0, Kv)                                      \
    do {                                                                       \
        const int NK = (Kv) >> 6;                                              \
        gemm_issue_stage(gsm,          Af, Bf, m0, n0, Kv, 0,  tid);           \
        CP_COMMIT();                                                           \
        gemm_issue_stage(gsm + GSTAGE, Af, Bf, m0, n0, Kv, 64, tid);           \
        CP_COMMIT();                                                           \
        int stg_ = 0;                                                          \
        for (int i = 0; i < NK; i++) {                                         \
            if (i + 1 < NK) { CP_WAIT1(); } else { CP_WAIT0(); }               \
            __syncthreads();                                                   \
            if (i + 2 < NK) {                                                  \
                int nst_ = stg_ + 2; if (nst_ >= 3) nst_ -= 3;                 \
                gemm_issue_stage(gsm + nst_ * GSTAGE,                          \
                                 Af, Bf, m0, n0, Kv, (i + 2) * 64, tid);       \
                CP_COMMIT();                                                   \
            }                                                                  \
            uint32_t uS  = uG + (uint32_t)(stg_ * GSTAGE);                     \
            uint32_t uAf = uS;                                                 \
            uint32_t uBf = uS + GT_BYTES;                                      \
            _Pragma("unroll")                                                  \
            for (int kk = 0; kk < 4; kk++) {                                   \
                uint32_t kb = kk * 32;                                         \
                uint32_t a4[2][4];                                             \
                _Pragma("unroll")                                              \
                for (int ii = 0; ii < 2; ii++)                                 \
                    ldsm_x4(a4[ii], uAf + SW128(baseA[ii] + kb));              \
                _Pragma("unroll")                                              \
                for (int jp = 0; jp < 4; jp++) {                               \
                    uint32_t b4[4];                                            \
                    ldsm_x4(b4, uBf + SW128(baseB[jp] + kb));                  \
                    _Pragma("unroll")                                          \
                    for (int jj = 0; jj < 2; jj++) {                           \
                        int j = jp * 2 + jj;                                   \
                        _Pragma("unroll")                                      \
                        for (int ii = 0; ii < 2; ii++)                         \
                            mma16816(acc[ii][j], a4[ii], b4 + 2 * jj);         \
                    }                                                          \
                }                                                              \
            }                                                                  \
            stg_ = stg_ + 1; if (stg_ >= 3) stg_ = 0;                          \
        }                                                                      \
    } while (0)

#define GEMM_PROLOG()                                                          \
    extern __shared__ char gsm[];                                              \
    int tid = threadIdx.x, lane = tid & 31, w = tid >> 5;                      \
    int g = lane >> 2, qi = lane & 3;                                          \
    int wm = w >> 1, wn = w & 1;                                               \
    int m0 = blockIdx.y * 128, n0 = blockIdx.x * 128;                          \
    uint32_t uG = smem_to_u32(gsm);                                            \
    uint32_t baseA[2], baseB[4];                                               \
    _Pragma("unroll")                                                          \
    for (int i = 0; i < 2; i++)                                                \
        baseA[i] = (uint32_t)((wm * 32 + i * 16 + (lane & 15)) * 128           \
                              + (lane >> 4) * 16);                             \
    _Pragma("unroll")                                                          \
    for (int jp = 0; jp < 4; jp++)                                             \
        baseB[jp] = (uint32_t)((wn * 64 + jp * 16 + (lane >> 4) * 8            \
                                + (lane & 7)) * 128 + ((lane >> 3) & 1) * 16); \
    float acc[2][8][4];                                                        \
    _Pragma("unroll")                                                          \
    for (int i = 0; i < 2; i++)                                                \
        _Pragma("unroll")                                                      \
        for (int j = 0; j < 8; j++)                                            \
            _Pragma("unroll")                                                  \
            for (int e = 0; e < 4; e++) acc[i][j][e] = 0.f;

// ---------------- generic GEMM (out-proj): fp32 C + bias ----------------
__global__ __launch_bounds__(256, 2) void gemm_mma(
    const __half* __restrict__ Af, const __half* __restrict__ Bf,
    const float* __restrict__ bias, float* __restrict__ C, int M, int N, int K)
{
    GEMM_PROLOG();
    GEMM_MAINLOOP(Af, Bf, m0, n0, K);

    #pragma unroll
    for (int i = 0; i < 2; i++) {
        int r0 = m0 + wm * 32 + i * 16 + g;
        #pragma unroll
        for (int j = 0; j < 8; j++) {
            int col = n0 + wn * 64 + j * 8 + 2 * qi;
            float b0 = __ldg(&bias[col]), b1 = __ldg(&bias[col + 1]);
            float2 v0 = make_float2(acc[i][j][0] + b0, acc[i][j][1] + b1);
            float2 v1 = make_float2(acc[i][j][2] + b0, acc[i][j][3] + b1);
            *(float2*)&C[(size_t)r0 * N + col]       = v0;
            *(float2*)&C[(size_t)(r0 + 8) * N + col] = v1;
        }
    }
}

// ---------------- fused QKV GEMM: bias + per-head LN + RoPE (table) epilogue ----------------
__global__ __launch_bounds__(256, 2) void gemm_qkv(
    const __half* __restrict__ Af, const __half* __restrict__ Bf,
    const float* __restrict__ bias,
    const float* __restrict__ q_scale, const float* __restrict__ k_scale,
    const float* __restrict__ ropeC, const float* __restrict__ ropeS,
    __half* __restrict__ qf, __half* __restrict__ kf, __half* __restrict__ vf)
{
    GEMM_PROLOG();
    GEMM_MAINLOOP(Af, Bf, m0, n0, D_);

    int region = n0 >> 10;                  // 0=q, 1=k, 2=v
    int hh = ((n0 & 1023) >> 6) + wn;       // head
    #pragma unroll
    for (int i = 0; i < 2; i++) {
        #pragma unroll
        for (int half = 0; half < 2; half++) {
            int r = m0 + wm * 32 + i * 16 + g + half * 8;
            int s = r & (S_ - 1), bb = r >> 11;
            size_t obase = (((size_t)(bb * H_ + hh)) * S_ + s) * HD_;

            float x[16];
            #pragma unroll
            for (int j = 0; j < 8; j++) {
                int col = n0 + wn * 64 + j * 8 + 2 * qi;
                x[2 * j]     = acc[i][j][half * 2]     + __ldg(&bias[col]);
                x[2 * j + 1] = acc[i][j][half * 2 + 1] + __ldg(&bias[col + 1]);
            }

            if (region == 2) {
                #pragma unroll
                for (int j = 0; j < 8; j++) {
                    int d = j * 8 + 2 * qi;
                    *(__half2*)&vf[obase + d] = __floats2half2_rn(x[2*j], x[2*j+1]);
                }
            } else {
                float sum = 0.f, sq = 0.f;
                #pragma unroll
                for (int t = 0; t < 16; t++) { sum += x[t]; sq += x[t] * x[t]; }
                sum += __shfl_xor_sync(0xffffffffu, sum, 1);
                sum += __shfl_xor_sync(0xffffffffu, sum, 2);
                sq  += __shfl_xor_sync(0xffffffffu, sq, 1);
                sq  += __shfl_xor_sync(0xffffffffu, sq, 2);
                float mu = sum * (1.0f / HD_);
                float rstd = rsqrtf(sq * (1.0f / HD_) - mu * mu + EPS);
                const float* sc = (region == 0) ? q_scale : k_scale;
                #pragma unroll
                for (int j = 0; j < 8; j++) {
                    int d = j * 8 + 2 * qi;
                    x[2 * j]     = (x[2 * j]     - mu) * rstd * __ldg(&sc[d]);
                    x[2 * j + 1] = (x[2 * j + 1] - mu) * rstd * __ldg(&sc[d + 1]);
                }
                #pragma unroll
                for (int j = 0; j < 4; j++) {
                    int d = j * 8 + 2 * qi;      // < 32
                    float2 cs2 = *(const float2*)&ropeC[s * 32 + d];
                    float2 sn2 = *(const float2*)&ropeS[s * 32 + d];
                    float cs[2] = {cs2.x, cs2.y};
                    float sn[2] = {sn2.x, sn2.y};
                    #pragma unroll
                    for (int c = 0; c < 2; c++) {
                        float lo = x[2 * j + c], hi = x[2 * (j + 4) + c];
                        x[2 * j + c]       = lo * cs[c] - hi * sn[c];
                        x[2 * (j + 4) + c] = hi * cs[c] + lo * sn[c];
                    }
                }
                if (region == 0) {
                    #pragma unroll
                    for (int j = 0; j < 8; j++) {
                        int d = j * 8 + 2 * qi;
                        *(__half2*)&qf[obase + d] =
                            __floats2half2_rn(x[2*j] * 0.125f, x[2*j+1] * 0.125f);
                    }
                } else {
                    #pragma unroll
                    for (int j = 0; j < 8; j++) {
                        int d = j * 8 + 2 * qi;
                        *(__half2*)&kf[obase + d] = __floats2half2_rn(x[2*j], x[2*j+1]);
                    }
                }
            }
        }
    }
}

// ---------------- flash attention: 3 CTAs/SM, Q hoisted, 3-stage KV ring ----------------
#define LQ 72
#define KVT (64 * LQ)
#define KVSTG (2 * KVT)
#define FL_SMEM ((128 * LQ + 3 * KVSTG) * (int)sizeof(__half))

__device__ __forceinline__ void flash_issue_kv(
    __half* st,
    const __half* __restrict__ Kp, const __half* __restrict__ Vp,
    int j0, int tid)
{
    int r = tid >> 2, c = (tid & 3) * 16;
    size_t go = (size_t)(j0 + r) * HD_ + c;
    int so = r * LQ + c;
    cp16(st + so,           Kp + go);
    cp16(st + so + 8,       Kp + go + 8);
    cp16(st + KVT + so,     Vp + go);
    cp16(st + KVT + so + 8, Vp + go + 8);
}

__global__ __launch_bounds__(256, 3) void flash_mma(
    const __half* __restrict__ Qf_, const __half* __restrict__ Kf_,
    const __half* __restrict__ Vf_, __half* __restrict__ O_)
{
    extern __shared__ __half fsm[];
    __half* sQ  = fsm;                 // [128][LQ]
    __half* sKV = sQ + 128 * LQ;

    int tid = threadIdx.x, lane = tid & 31, wid = tid >> 5;
    int g = lane >> 2, qi = lane & 3;
    int bh = blockIdx.y;
    int b = bh >> 4, h = bh & 15;
    int q0 = blockIdx.x * 128;
    size_t hbase = (size_t)bh * S_ * HD_;
    const __half* Qfp = Qf_ + hbase;
    const __half* Kfp = Kf_ + hbase;
    const __half* Vfp = Vf_ + hbase;

    int wr = wid * 16;
    uint32_t uQ  = smem_to_u32(sQ);
    uint32_t uKV = smem_to_u32(sKV);

    uint32_t offQ = ((wr + (lane & 15)) * LQ + (lane >> 4) * 8) * 2;
    uint32_t offK[4], offV[4];
    #pragma unroll
    for (int tp = 0; tp < 4; tp++)
        offK[tp] = ((tp * 16 + (lane >> 4) * 8 + (lane & 7)) * LQ
                    + ((lane >> 3) & 1) * 8) * 2;
    #pragma unroll
    for (int tdp = 0; tdp < 4; tdp++)
        offV[tdp] = ((((lane >> 3) & 1) * 8 + (lane & 7)) * LQ
                     + (2 * tdp + (lane >> 4)) * 8) * 2;

    #pragma unroll
    for (int i = 0; i < 4; i++) {
        int u = tid + i * 256;
        int r = u >> 3, c = (u & 7) * 8;
        *(uint4*)&sQ[r * LQ + c] = *(const uint4*)&Qfp[(size_t)(q0 + r) * HD_ + c];
    }
    flash_issue_kv(sKV,         Kfp, Vfp, 0,  tid);
    CP_COMMIT();
    flash_issue_kv(sKV + KVSTG, Kfp, Vfp, 64, tid);
    CP_COMMIT();
    __syncthreads();

    uint32_t qfrag[4][4];
    #pragma unroll
    for (int u = 0; u < 4; u++)
        ldsm_x4(qfrag[u], uQ + offQ + u * 32);

    float o[8][4];
    #pragma unroll
    for (int t = 0; t < 8; t++)
        #pragma unroll
        for (int e = 0; e < 4; e++) o[t][e] = 0.f;
    float m_g = -1e30f, m_g8 = -1e30f, l_g = 0.f, l_g8 = 0.f;

    const int NT = S_ / 64;
    int stg = 0;
    for (int kt = 0; kt < NT; kt++) {
        if (kt + 1 < NT) { CP_WAIT1(); } else { CP_WAIT0(); }
        __syncthreads();

        if (kt + 2 < NT) {
            int nst = stg + 2; if (nst >= 3) nst -= 3;
            flash_issue_kv(sKV + nst * KVSTG, Kfp, Vfp, (kt + 2) * 64, tid);
            CP_COMMIT();
        }

        uint32_t uS = uKV + (uint32_t)(stg * KVSTG) * 2;
        uint32_t uK = uS;
        uint32_t uV = uS + KVT * 2;

        float s[8][4];
        #pragma unroll
        for (int t = 0; t < 8; t++)
            #pragma unroll
            for (int e = 0; e < 4; e++) s[t][e] = 0.f;

        #pragma unroll
        for (int u = 0; u < 4; u++) {
            #pragma unroll
            for (int tp = 0; tp < 4; tp++) {
                uint32_t b4[4];
                ldsm_x4(b4, uK + offK[tp] + u * 32);
                mma16816(s[2 * tp],     qfrag[u], b4);
                mma16816(s[2 * tp + 1], qfrag[u], b4 + 2);
            }
        }

        float mt_g = -1e30f, mt_g8 = -1e30f;
        #pragma unroll
        for (int t = 0; t < 8; t++) {
            mt_g  = fmaxf(mt_g,  fmaxf(s[t][0], s[t][1]));
            mt_g8 = fmaxf(mt_g8, fmaxf(s[t][2], s[t][3]));
        }
        mt_g  = fmaxf(mt_g,  __shfl_xor_sync(0xffffffffu, mt_g, 1));
        mt_g  = fmaxf(mt_g,  __shfl_xor_sync(0xffffffffu, mt_g, 2));
        mt_g8 = fmaxf(mt_g8, __shfl_xor_sync(0xffffffffu, mt_g8, 1));
        mt_g8 = fmaxf(mt_g8, __shfl_xor_sync(0xffffffffu, mt_g8, 2));
        float mn_g = fmaxf(m_g, mt_g), mn_g8 = fmaxf(m_g8, mt_g8);
        float al_g = __expf(m_g - mn_g), al_g8 = __expf(m_g8 - mn_g8);
        m_g = mn_g; m_g8 = mn_g8;

        uint32_t ph01[8], ph23[8];
        float sum_g = 0.f, sum_g8 = 0.f;
        #pragma unroll
        for (int t = 0; t < 8; t++) {
            float p0 = __expf(s[t][0] - mn_g);
            float p1 = __expf(s[t][1] - mn_g);
            float p2 = __expf(s[t][2] - mn_g8);
            float p3 = __expf(s[t][3] - mn_g8);
            sum_g += p0 + p1; sum_g8 += p2 + p3;
            ph01[t] = h2u(__floats2half2_rn(p0, p1));
            ph23[t] = h2u(__floats2half2_rn(p2, p3));
        }
        sum_g  += __shfl_xor_sync(0xffffffffu, sum_g, 1);
        sum_g  += __shfl_xor_sync(0xffffffffu, sum_g, 2);
        sum_g8 += __shfl_xor_sync(0xffffffffu, sum_g8, 1);
        sum_g8 += __shfl_xor_sync(0xffffffffu, sum_g8, 2);
        l_g  = l_g  * al_g  + sum_g;
        l_g8 = l_g8 * al_g8 + sum_g8;

        #pragma unroll
        for (int t = 0; t < 8; t++) {
            o[t][0] *= al_g;  o[t][1] *= al_g;
            o[t][2] *= al_g8; o[t][3] *= al_g8;
        }

        #pragma unroll
        for (int u = 0; u < 4; u++) {
            uint32_t pah[4] = {ph01[2*u], ph23[2*u], ph01[2*u+1], ph23[2*u+1]};
            uint32_t ubase = u * 16 * LQ * 2;
            #pragma unroll
            for (int tdp = 0; tdp < 4; tdp++) {
                uint32_t bv4[4];
                ldsm_x4_t(bv4, uV + offV[tdp] + ubase);
                mma16816(o[2 * tdp],     pah, bv4);
                mma16816(o[2 * tdp + 1], pah, bv4 + 2);
            }
        }

        stg = stg + 1; if (stg >= 3) stg = 0;
    }

    float iv_g = 1.f / l_g, iv_g8 = 1.f / l_g8;
    size_t ob  = ((size_t)(b * S_ + q0 + wr + g)     * H_ + h) * HD_;
    size_t ob8 = ((size_t)(b * S_ + q0 + wr + g + 8) * H_ + h) * HD_;
    #pragma unroll
    for (int td = 0; td < 8; td++) {
        int d = 8 * td + 2 * qi;
        *(uint32_t*)&O_[ob + d]  = h2u(__floats2half2_rn(o[td][0] * iv_g,
                                                         o[td][1] * iv_g));
        *(uint32_t*)&O_[ob8 + d] = h2u(__floats2half2_rn(o[td][2] * iv_g8,
                                                         o[td][3] * iv_g8));
    }
}

// ---------------- launcher ----------------
extern "C" void kernel_launch(void* const* d_in, const int* in_sizes, int n_in,
                              void* d_out, int out_size)
{
    const float* x        = (const float*)d_in[0];
    const float* w_qkv    = (const float*)d_in[1];
    const float* b_qkv    = (const float*)d_in[2];
    const float* w_out    = (const float*)d_in[3];
    const float* b_out    = (const float*)d_in[4];
    const float* ln_scale = (const float*)d_in[5];
    const float* ln_bias  = (const float*)d_in[6];
    const float* q_scale  = (const float*)d_in[7];
    const float* k_scale  = (const float*)d_in[8];
    float* out = (float*)d_out;

    __half *xn, *wq, *wo, *attn, *qf, *kf, *vf;
    float *rC, *rS;
    cudaGetSymbolAddress((void**)&xn,   g_xn);
    cudaGetSymbolAddress((void**)&wq,   g_wqT);
    cudaGetSymbolAddress((void**)&wo,   g_woT);
    cudaGetSymbolAddress((void**)&qf,   g_qf);
    cudaGetSymbolAddress((void**)&kf,   g_kf);
    cudaGetSymbolAddress((void**)&vf,   g_vf);
    cudaGetSymbolAddress((void**)&attn, g_attn);
    cudaGetSymbolAddress((void**)&rC,   g_ropeC);
    cudaGetSymbolAddress((void**)&rS,   g_ropeS);

    cudaFuncSetAttribute(gemm_mma,
        cudaFuncAttributeMaxDynamicSharedMemorySize, GEMM_SMEM);
    cudaFuncSetAttribute(gemm_qkv,
        cudaFuncAttributeMaxDynamicSharedMemorySize, GEMM_SMEM);
    cudaFuncSetAttribute(flash_mma,
        cudaFuncAttributeMaxDynamicSharedMemorySize, FL_SMEM);

    // 1. fused prep: LN + weight casts + rope tables
    prep_kernel<<<PREP_BLOCKS, 256>>>(x, ln_scale, ln_bias, xn,
                                      w_qkv, wq, w_out, wo, rC, rS);

    // 2. fused QKV GEMM + per-head LN + RoPE
    gemm_qkv<<<dim3((3 * D_) / 128, ROWS / 128), 256, GEMM_SMEM>>>(
        xn, wq, b_qkv, q_scale, k_scale, rC, rS, qf, kf, vf);

    // 3. flash attention (3 CTAs/SM)
    flash_mma<<<dim3(S_ / 128, B_ * H_), 256, FL_SMEM>>>(qf, kf, vf, attn);

    // 4. output GEMM
    gemm_mma<<<dim3(D_ / 128, ROWS / 128), 256, GEMM_SMEM>>>(
        attn, wo, b_out, out, ROWS, D_, D_);
}